// round 11
// baseline (speedup 1.0000x reference)
#include <cuda_runtime.h>
#include <cuda_fp16.h>
#include <cstdint>

#define NNODES 20000
#define NEDGES 640000
#define RREL 64
#define BBASIS 16
#define DIN 128
#define KG 2048
#define KTOT 2176
#define AROWS 20096          /* padded; pad rows stay zero forever */
#define NTILES 157           /* ceil(20000/128) */
#define GEMM_GRID 296
#define EDGE_GRID 740
#define KSTAGES 68           /* 2176 / 32 */

/* GEMM smem stage layout (bytes), 80B row stride keeps ldmatrix conflict-free */
#define SA 0
#define SB 10240
#define STAGE_BYTES 20480
#define NSTAGE 4
#define SMEM_TOTAL (NSTAGE * STAGE_BYTES)

/* edge kernel smem strides */
#define XS_STRIDE 272        /* 256B row + 16B pad */
#define AT_STRIDE 48         /* 32B row + 16B pad */

typedef unsigned long long ull;

// ---------------- helpers ----------------

__device__ __forceinline__ uint32_t smem_u32(const void* p) {
    uint32_t a;
    asm("{ .reg .u64 t; cvta.to.shared.u64 t, %1; cvt.u32.u64 %0, t; }" : "=r"(a) : "l"(p));
    return a;
}

__device__ __forceinline__ void cp16(uint32_t dst, const void* src) {
    asm volatile("cp.async.cg.shared.global [%0], [%1], 16;" :: "r"(dst), "l"(src) : "memory");
}
__device__ __forceinline__ void cp_commit() {
    asm volatile("cp.async.commit_group;" ::: "memory");
}
template <int N>
__device__ __forceinline__ void cp_wait() {
    asm volatile("cp.async.wait_group %0;" :: "n"(N) : "memory");
}

__device__ __forceinline__ void ldx4(uint32_t* r, uint32_t addr) {
    asm volatile("ldmatrix.sync.aligned.m8n8.x4.shared.b16 {%0,%1,%2,%3}, [%4];"
        : "=r"(r[0]), "=r"(r[1]), "=r"(r[2]), "=r"(r[3]) : "r"(addr));
}
__device__ __forceinline__ void ldx4t(uint32_t* r, uint32_t addr) {
    asm volatile("ldmatrix.sync.aligned.m8n8.x4.trans.shared.b16 {%0,%1,%2,%3}, [%4];"
        : "=r"(r[0]), "=r"(r[1]), "=r"(r[2]), "=r"(r[3]) : "r"(addr));
}

__device__ __forceinline__ void mma_fp16(float* d, const uint32_t* a, const uint32_t* b) {
    asm volatile(
        "mma.sync.aligned.m16n8k16.row.col.f32.f16.f16.f32 "
        "{%0,%1,%2,%3}, {%4,%5,%6,%7}, {%8,%9}, {%0,%1,%2,%3};"
        : "+f"(d[0]), "+f"(d[1]), "+f"(d[2]), "+f"(d[3])
        : "r"(a[0]), "r"(a[1]), "r"(a[2]), "r"(a[3]), "r"(b[0]), "r"(b[1]));
}

// ---------------- scratch ----------------
__device__ __half g_Ah[(size_t)AROWS * KTOT];
__device__ __half g_Wh[(size_t)DIN * KTOT];   // [n][k]
__device__ __half g_xh[(size_t)NNODES * DIN]; // x in fp16
__device__ int g_cnt[NNODES];
__device__ int g_cur[NNODES];
__device__ int g_off[NNODES + 1];
__device__ uint2 g_edata[NEDGES];    // sorted packed: {src | et<<16, norm bits}
__device__ int g_tile;
__device__ int g_node;
__device__ int g_done;

// ---------------- hist + weight/x conversion + last-block scan ----------------

__global__ void k_histscan(const int* __restrict__ dst, int e,
                           const float* __restrict__ weight,
                           const float* __restrict__ loopw,
                           const float* __restrict__ x) {
    int i = blockIdx.x * blockDim.x + threadIdx.x;
    int nthreads = gridDim.x * blockDim.x;
    if (i < e) atomicAdd(&g_cnt[dst[i]], 1);
    if (i < DIN * KTOT) {
        int n = i & 127;
        int k = i >> 7;
        float w = (k < KG) ? weight[(size_t)k * 128 + n]
                           : loopw[(size_t)(k - KG) * 128 + n];
        g_Wh[(size_t)n * KTOT + k] = __float2half_rn(w);
    }
    for (int j = i; j < NNODES * DIN / 2; j += nthreads) {
        float2 v = ((const float2*)x)[j];
        ((__half2*)g_xh)[j] = __floats2half2_rn(v.x, v.y);
    }
    __threadfence();
    __shared__ int s_last;
    if (threadIdx.x == 0) s_last = atomicAdd(&g_done, 1);
    __syncthreads();
    if (s_last == (int)gridDim.x - 1) {
        __shared__ int part[256];
        int t = threadIdx.x;
        const int chunk = 79;
        int base = t * chunk;
        int s = 0;
        for (int j = 0; j < chunk; j++) {
            int idx = base + j;
            if (idx < NNODES) s += g_cnt[idx];
        }
        part[t] = s;
        __syncthreads();
        for (int d = 1; d < 256; d <<= 1) {
            int v = (t >= d) ? part[t - d] : 0;
            __syncthreads();
            part[t] += v;
            __syncthreads();
        }
        int run = (t == 0) ? 0 : part[t - 1];
        for (int j = 0; j < chunk; j++) {
            int idx = base + j;
            if (idx < NNODES) { g_off[idx] = run; run += g_cnt[idx]; }
        }
        if (t == 255) g_off[NNODES] = run;
        if (t == 0) { g_done = 0; g_tile = 0; g_node = 0; }
    }
}

__global__ void k_scatter(const int* __restrict__ dst, const int* __restrict__ src,
                          const int* __restrict__ et, const float* __restrict__ norm,
                          int e) {
    int i = blockIdx.x * blockDim.x + threadIdx.x;
    if (i < e) {
        int d = dst[i];
        int p = g_off[d] + atomicAdd(&g_cur[d], 1);
        g_edata[p] = make_uint2((uint32_t)src[i] | ((uint32_t)et[i] << 16),
                                __float_as_uint(norm[i]));
    }
}

// ---------------- tensor-core edge accumulation, 3-buffer pipeline ----------------
// Per dst node: G[16,128] = A[16,deg] @ Xs[deg,128] via m16n8k16 chunks of 16
// edges. Chunk c's gather latency hidden: issue chunk c+2 while computing c.

__global__ void __launch_bounds__(256) k_edge_tc(const float* __restrict__ wcomp)
{
    __shared__ float wc_s[RREL * BBASIS];
    __shared__ __align__(16) char XS[3][16 * XS_STRIDE];
    __shared__ __align__(16) char AT[3][16 * AT_STRIDE];
    __shared__ int s_node;

    int t = threadIdx.x;
    int l = t & 31, w = t >> 5;

    for (int i = t; i < RREL * BBASIS; i += 256) wc_s[i] = wcomp[i];
    const float4* wc4 = (const float4*)wc_s;

    int eidx = t >> 4;        // edge slot 0..15
    int seg  = t & 15;        // 16B segment within 256B row
    bool abuild = (eidx == seg);

    uint32_t xs_base[3] = { smem_u32(XS[0]), smem_u32(XS[1]), smem_u32(XS[2]) };
    uint32_t at_base[3] = { smem_u32(AT[0]), smem_u32(AT[1]), smem_u32(AT[2]) };

    uint32_t a_off = (uint32_t)(((l & 7) + ((l >> 4) & 1) * 8) * AT_STRIDE
                                + ((l >> 3) & 1) * 16);
    uint32_t b_off = (uint32_t)((l & 15) * XS_STRIDE + 32 * w + ((l >> 4) & 1) * 16);

    for (;;) {
        __syncthreads();
        if (t == 0) s_node = atomicAdd(&g_node, 1);
        __syncthreads();
        int d = s_node;
        if (d >= NNODES) break;

        int k0 = g_off[d], k1 = g_off[d + 1];
        int nch = (k1 - k0 + 15) >> 4;

        float acc[2][4];
#pragma unroll
        for (int j = 0; j < 2; j++)
#pragma unroll
            for (int q = 0; q < 4; q++) acc[j][q] = 0.f;

        // stage(c, buf) as a lambda-ish macro
#define EDGE_STAGE(c, buf) do {                                                   \
            int kk = k0 + (c) * 16 + eidx;                                        \
            uint2 en = __ldg(&g_edata[min(kk, k1 - 1)]);                          \
            bool v = kk < k1;                                                     \
            int s = en.x & 0xFFFF;                                                \
            cp16(xs_base[buf] + eidx * XS_STRIDE + seg * 16,                      \
                 g_xh + (size_t)s * DIN + seg * 8);                               \
            if (abuild) {                                                         \
                float nv = v ? __uint_as_float(en.y) : 0.f;                       \
                int r = en.x >> 16;                                               \
                float4 w0 = wc4[r * 4 + 0], w1 = wc4[r * 4 + 1];                  \
                float4 w2 = wc4[r * 4 + 2], w3 = wc4[r * 4 + 3];                  \
                __half2 h[8];                                                     \
                h[0] = __floats2half2_rn(w0.x * nv, w0.y * nv);                   \
                h[1] = __floats2half2_rn(w0.z * nv, w0.w * nv);                   \
                h[2] = __floats2half2_rn(w1.x * nv, w1.y * nv);                   \
                h[3] = __floats2half2_rn(w1.z * nv, w1.w * nv);                   \
                h[4] = __floats2half2_rn(w2.x * nv, w2.y * nv);                   \
                h[5] = __floats2half2_rn(w2.z * nv, w2.w * nv);                   \
                h[6] = __floats2half2_rn(w3.x * nv, w3.y * nv);                   \
                h[7] = __floats2half2_rn(w3.z * nv, w3.w * nv);                   \
                *(uint4*)(AT[buf] + eidx * AT_STRIDE)      = *(uint4*)&h[0];      \
                *(uint4*)(AT[buf] + eidx * AT_STRIDE + 16) = *(uint4*)&h[4];      \
            }                                                                     \
        } while (0)

        if (nch > 0) {
            // prologue: always commit exactly two groups
            EDGE_STAGE(0, 0);
            cp_commit();
            if (nch > 1) EDGE_STAGE(1, 1);
            cp_commit();

#pragma unroll 1
            for (int c = 0; c < nch; c++) {
                cp_wait<1>();            // chunk c's group complete
                __syncthreads();         // publish to all; prior ldsm done
                if (c + 2 < nch) {
                    int nb = c + 2; nb -= (nb >= 3) ? 3 : 0; nb -= (nb >= 3) ? 3 : 0;
                    EDGE_STAGE(c + 2, (c + 2) % 3);
                }
                cp_commit();             // unconditional: keeps wait counts exact

                int buf = c % 3;
                uint32_t af[4], bf[4];
                ldx4t(af, at_base[buf] + a_off);
                ldx4t(bf, xs_base[buf] + b_off);
                mma_fp16(acc[0], af, &bf[0]);
                mma_fp16(acc[1], af, &bf[2]);
            }
        }
#undef EDGE_STAGE

        // epilogue: store G rows + self-loop
        size_t base = (size_t)d * KTOT;
        int row = l >> 2, cc = 2 * (l & 3);
#pragma unroll
        for (int j = 0; j < 2; j++) {
            int col = w * 16 + j * 8 + cc;
            __half2 h01 = __floats2half2_rn(acc[j][0], acc[j][1]);
            __half2 h23 = __floats2half2_rn(acc[j][2], acc[j][3]);
            *(__half2*)(g_Ah + base + (size_t)row * 128 + col)       = h01;
            *(__half2*)(g_Ah + base + (size_t)(row + 8) * 128 + col) = h23;
        }
        if (t < 64)
            ((uint32_t*)(g_Ah + base + KG))[t] =
                ((const uint32_t*)(g_xh + (size_t)d * DIN))[t];
    }
}

// ---------------- fp16 mma GEMM: BM=128, BN=128, BK=32, 4-stage ----------------
// 8 warps as 2m x 4n, warp tile 64x32. B L2-traffic halved vs BM=64.

extern __shared__ char dynsmem[];

__global__ void __launch_bounds__(256) k_gemm_mma(const float* __restrict__ bias,
                                                  float* __restrict__ out)
{
    __shared__ int s_tile;
    int t = threadIdx.x;
    int l = t & 31, wid = t >> 5;

    // re-zero sort counters for next graph replay
    int gid = blockIdx.x * 256 + t;
    if (gid < NNODES) { g_cnt[gid] = 0; g_cur[gid] = 0; }

    uint32_t su = smem_u32(dynsmem);

    int wm = (wid & 1) * 64;
    int wn = (wid >> 1) * 32;

    uint32_t aoff[4], boff[2];
#pragma unroll
    for (int mf = 0; mf < 4; mf++)
        aoff[mf] = (uint32_t)(SA + (wm + mf * 16 + (l & 15)) * 80 + (l >> 4) * 16);
#pragma unroll
    for (int nb = 0; nb < 2; nb++)
        boff[nb] = (uint32_t)(SB + (wn + nb * 16 + ((l >> 4) << 3) + (l & 7)) * 80
                              + ((l >> 3) & 1) * 16);

    // staging: thread covers row t>>1, 32B half (t&1) of the 64B row (2 cp16)
    int arow = t >> 1;
    int ahseg = (t & 1) * 16;            // halves offset
    uint32_t dA = (uint32_t)(SA + arow * 80 + (t & 1) * 32);
    uint32_t dB = (uint32_t)(SB + arow * 80 + (t & 1) * 32);
    const __half* pB = g_Wh + (size_t)arow * KTOT + ahseg;

    for (;;) {
        __syncthreads();
        if (t == 0) s_tile = atomicAdd(&g_tile, 1);
        __syncthreads();
        int tile = s_tile;
        if (tile >= NTILES) break;
        int tileM = tile * 128;

        const __half* pA = g_Ah + (size_t)(tileM + arow) * KTOT + ahseg;

        float acc[4][4][4];
#pragma unroll
        for (int mf = 0; mf < 4; mf++)
#pragma unroll
            for (int nf = 0; nf < 4; nf++)
#pragma unroll
                for (int q = 0; q < 4; q++) acc[mf][nf][q] = 0.f;

#pragma unroll
        for (int p = 0; p < 3; p++) {
            uint32_t sb = su + p * STAGE_BYTES;
            int koff = p * 32;
            cp16(sb + dA,      pA + koff);
            cp16(sb + dA + 16, pA + koff + 8);
            cp16(sb + dB,      pB + koff);
            cp16(sb + dB + 16, pB + koff + 8);
            cp_commit();
        }

        int stg = 0;
#pragma unroll 1
        for (int it = 0; it < KSTAGES; it++) {
            cp_wait<2>();
            __syncthreads();
            if (it + 3 < KSTAGES) {
                int pst = (stg + 3) & 3;
                uint32_t sb = su + pst * STAGE_BYTES;
                int koff = (it + 3) * 32;
                cp16(sb + dA,      pA + koff);
                cp16(sb + dA + 16, pA + koff + 8);
                cp16(sb + dB,      pB + koff);
                cp16(sb + dB + 16, pB + koff + 8);
            }
            cp_commit();

            uint32_t sb = su + stg * STAGE_BYTES;
#pragma unroll
            for (int ks = 0; ks < 2; ks++) {
                uint32_t ah[4][4], bh[4][2];
#pragma unroll
                for (int mf = 0; mf < 4; mf++)
                    ldx4(ah[mf], sb + aoff[mf] + ks * 32);
                {
                    uint32_t r[4];
                    ldx4(r, sb + boff[0] + ks * 32);
                    bh[0][0] = r[0]; bh[0][1] = r[1]; bh[1][0] = r[2]; bh[1][1] = r[3];
                    ldx4(r, sb + boff[1] + ks * 32);
                    bh[2][0] = r[0]; bh[2][1] = r[1]; bh[3][0] = r[2]; bh[3][1] = r[3];
                }
#pragma unroll
                for (int mf = 0; mf < 4; mf++)
#pragma unroll
                    for (int nf = 0; nf < 4; nf++)
                        mma_fp16(acc[mf][nf], ah[mf], bh[nf]);
            }
            stg = (stg + 1) & 3;
        }

        // epilogue: bias + relu + store
#pragma unroll
        for (int mf = 0; mf < 4; mf++) {
#pragma unroll
            for (int nf = 0; nf < 4; nf++) {
                int col = wn + nf * 8 + 2 * (l & 3);
                float b0 = bias[col], b1 = bias[col + 1];
                int r0 = tileM + wm + mf * 16 + (l >> 2);
                int r1 = r0 + 8;
                if (r0 < NNODES) {
                    float2 o;
                    o.x = fmaxf(acc[mf][nf][0] + b0, 0.f);
                    o.y = fmaxf(acc[mf][nf][1] + b1, 0.f);
                    *(float2*)(out + (size_t)r0 * DIN + col) = o;
                }
                if (r1 < NNODES) {
                    float2 o;
                    o.x = fmaxf(acc[mf][nf][2] + b0, 0.f);
                    o.y = fmaxf(acc[mf][nf][3] + b1, 0.f);
                    *(float2*)(out + (size_t)r1 * DIN + col) = o;
                }
            }
        }
    }
}

// ---------------- launch ----------------

extern "C" void kernel_launch(void* const* d_in, const int* in_sizes, int n_in,
                              void* d_out, int out_size) {
    const float* x      = (const float*)d_in[0];
    const float* weight = (const float*)d_in[1];
    const float* wcomp  = (const float*)d_in[2];
    const float* bias   = (const float*)d_in[3];
    const float* loopw  = (const float*)d_in[4];
    const float* norm   = (const float*)d_in[5];
    const int*   src    = (const int*)d_in[6];
    const int*   dst    = (const int*)d_in[7];
    const int*   et     = (const int*)d_in[8];
    float* out = (float*)d_out;

    int E = in_sizes[6];

    cudaFuncSetAttribute(k_gemm_mma, cudaFuncAttributeMaxDynamicSharedMemorySize,
                         SMEM_TOTAL);

    k_histscan<<<(E + 255) / 256, 256>>>(dst, E, weight, loopw, x);
    k_scatter<<<(E + 255) / 256, 256>>>(dst, src, et, norm, E);
    k_edge_tc<<<EDGE_GRID, 256>>>(wcomp);
    k_gemm_mma<<<GEMM_GRID, 256, SMEM_TOTAL>>>(bias, out);
}

// round 12
// speedup vs baseline: 1.0805x; 1.0805x over previous
#include <cuda_runtime.h>
#include <cuda_fp16.h>
#include <cstdint>

#define NNODES 20000
#define NEDGES 640000
#define RREL 64
#define BBASIS 16
#define DIN 128
#define KG 2048
#define KTOT 2176
#define AROWS 20096          /* padded; pad rows stay zero forever */
#define NTILES 313           /* ceil(20000/64) */
#define GEMM_GRID 444
#define EDGE_GRID 296
#define KSTAGES 68           /* 2176 / 32 */

/* GEMM smem stage layout (bytes), 80B row stride keeps ldmatrix conflict-free */
#define GSA 0
#define GSB 5120
#define GSTAGE 15360
#define GNSTAGE 4
#define GEMM_SMEM (GNSTAGE * GSTAGE)   /* 61440 */

/* edge kernel: per-warp double-buffered regions */
#define XS_STRIDE 272        /* 256B row + 16B pad */
#define AT_STRIDE 48         /* 32B row + 16B pad */
#define WXS (16 * XS_STRIDE) /* 4352 */
#define WAT (16 * AT_STRIDE) /* 768  */
#define WBUF (WXS + WAT)     /* 5120 */
#define WREGION (2 * WBUF)   /* 10240 per warp */
#define EDGE_SMEM (8 * WREGION)  /* 81920 */

typedef unsigned long long ull;

// ---------------- helpers ----------------

__device__ __forceinline__ uint32_t smem_u32(const void* p) {
    uint32_t a;
    asm("{ .reg .u64 t; cvta.to.shared.u64 t, %1; cvt.u32.u64 %0, t; }" : "=r"(a) : "l"(p));
    return a;
}

__device__ __forceinline__ void cp16(uint32_t dst, const void* src) {
    asm volatile("cp.async.cg.shared.global [%0], [%1], 16;" :: "r"(dst), "l"(src) : "memory");
}
__device__ __forceinline__ void cp_commit() {
    asm volatile("cp.async.commit_group;" ::: "memory");
}
template <int N>
__device__ __forceinline__ void cp_wait() {
    asm volatile("cp.async.wait_group %0;" :: "n"(N) : "memory");
}

__device__ __forceinline__ void ldx4(uint32_t* r, uint32_t addr) {
    asm volatile("ldmatrix.sync.aligned.m8n8.x4.shared.b16 {%0,%1,%2,%3}, [%4];"
        : "=r"(r[0]), "=r"(r[1]), "=r"(r[2]), "=r"(r[3]) : "r"(addr));
}
__device__ __forceinline__ void ldx4t(uint32_t* r, uint32_t addr) {
    asm volatile("ldmatrix.sync.aligned.m8n8.x4.trans.shared.b16 {%0,%1,%2,%3}, [%4];"
        : "=r"(r[0]), "=r"(r[1]), "=r"(r[2]), "=r"(r[3]) : "r"(addr));
}

__device__ __forceinline__ void mma_fp16(float* d, const uint32_t* a, const uint32_t* b) {
    asm volatile(
        "mma.sync.aligned.m16n8k16.row.col.f32.f16.f16.f32 "
        "{%0,%1,%2,%3}, {%4,%5,%6,%7}, {%8,%9}, {%0,%1,%2,%3};"
        : "+f"(d[0]), "+f"(d[1]), "+f"(d[2]), "+f"(d[3])
        : "r"(a[0]), "r"(a[1]), "r"(a[2]), "r"(a[3]), "r"(b[0]), "r"(b[1]));
}

// ---------------- scratch ----------------
__device__ __half g_Ah[(size_t)AROWS * KTOT];
__device__ __half g_Wh[(size_t)DIN * KTOT];   // [n][k]
__device__ __half g_xh[(size_t)NNODES * DIN]; // x in fp16
__device__ int g_cnt[NNODES];
__device__ int g_cur[NNODES];
__device__ int g_off[NNODES + 1];
__device__ uint2 g_edata[NEDGES];    // sorted packed: {src | et<<16, norm bits}
__device__ int g_tile;
__device__ int g_node;
__device__ int g_done;

// ---------------- hist + weight/x conversion + last-block scan ----------------

__global__ void k_histscan(const int* __restrict__ dst, int e,
                           const float* __restrict__ weight,
                           const float* __restrict__ loopw,
                           const float* __restrict__ x) {
    int i = blockIdx.x * blockDim.x + threadIdx.x;
    int nthreads = gridDim.x * blockDim.x;
    if (i < e) atomicAdd(&g_cnt[dst[i]], 1);
    if (i < DIN * KTOT) {
        int n = i & 127;
        int k = i >> 7;
        float w = (k < KG) ? weight[(size_t)k * 128 + n]
                           : loopw[(size_t)(k - KG) * 128 + n];
        g_Wh[(size_t)n * KTOT + k] = __float2half_rn(w);
    }
    for (int j = i; j < NNODES * DIN / 2; j += nthreads) {
        float2 v = ((const float2*)x)[j];
        ((__half2*)g_xh)[j] = __floats2half2_rn(v.x, v.y);
    }
    __threadfence();
    __shared__ int s_last;
    if (threadIdx.x == 0) s_last = atomicAdd(&g_done, 1);
    __syncthreads();
    if (s_last == (int)gridDim.x - 1) {
        __shared__ int part[256];
        int t = threadIdx.x;
        const int chunk = 79;
        int base = t * chunk;
        int s = 0;
        for (int j = 0; j < chunk; j++) {
            int idx = base + j;
            if (idx < NNODES) s += g_cnt[idx];
        }
        part[t] = s;
        __syncthreads();
        for (int d = 1; d < 256; d <<= 1) {
            int v = (t >= d) ? part[t - d] : 0;
            __syncthreads();
            part[t] += v;
            __syncthreads();
        }
        int run = (t == 0) ? 0 : part[t - 1];
        for (int j = 0; j < chunk; j++) {
            int idx = base + j;
            if (idx < NNODES) { g_off[idx] = run; run += g_cnt[idx]; }
        }
        if (t == 255) g_off[NNODES] = run;
        if (t == 0) { g_done = 0; g_tile = 0; g_node = 0; }
    }
}

__global__ void k_scatter(const int* __restrict__ dst, const int* __restrict__ src,
                          const int* __restrict__ et, const float* __restrict__ norm,
                          int e) {
    int i = blockIdx.x * blockDim.x + threadIdx.x;
    if (i < e) {
        int d = dst[i];
        int p = g_off[d] + atomicAdd(&g_cur[d], 1);
        g_edata[p] = make_uint2((uint32_t)src[i] | ((uint32_t)et[i] << 16),
                                __float_as_uint(norm[i]));
    }
}

// ---------------- warp-per-node tensor-core edge accumulation ----------------
// Each WARP owns one dst node: G[16,128] = A[16,deg] @ Xs[deg,128], chunks of
// 16 edges, per-warp double-buffered cp.async, no block barriers in the loop.
// Per chunk: 8 cp16/lane gather, lanes 0-15 build A cols, 1+8 trans-ldmatrix,
// 16 MMAs (covers all 128 cols).

extern __shared__ char dynsmem[];

__global__ void __launch_bounds__(256, 2) k_edge_tc(const float* __restrict__ wcomp)
{
    __shared__ float wc_s[RREL * BBASIS];

    int t = threadIdx.x;
    int l = t & 31, w = t >> 5;

    for (int i = t; i < RREL * BBASIS; i += 256) wc_s[i] = wcomp[i];
    __syncthreads();
    const float4* wc4 = (const float4*)wc_s;

    uint32_t wbase = smem_u32(dynsmem) + w * WREGION;
    uint32_t xsb[2] = { wbase, wbase + WBUF };
    uint32_t atb[2] = { wbase + WXS, wbase + WBUF + WXS };

    int er = l & 15;          // edge slot this lane stages
    int hh = l >> 4;          // which 128B half of the 256B row
    bool abuild = (l < 16);

    uint32_t a_off = (uint32_t)(((l & 7) + ((l >> 4) & 1) * 8) * AT_STRIDE
                                + ((l >> 3) & 1) * 16);
    uint32_t b_off = (uint32_t)((l & 15) * XS_STRIDE + ((l >> 4) & 1) * 16);

#define EDGE_STAGE(c, buf) do {                                                   \
        int kk = k0 + (c) * 16 + er;                                              \
        uint2 en = __ldg(&g_edata[min(kk, k1 - 1)]);                              \
        bool v = kk < k1;                                                         \
        int s = en.x & 0xFFFF;                                                    \
        uint32_t xdst = xsb[buf] + er * XS_STRIDE + hh * 128;                     \
        const __half* xsrc = g_xh + (size_t)s * DIN + hh * 64;                    \
        _Pragma("unroll")                                                         \
        for (int q = 0; q < 8; q++) cp16(xdst + q * 16, xsrc + q * 8);            \
        if (abuild) {                                                             \
            float nv = v ? __uint_as_float(en.y) : 0.f;                           \
            int r = en.x >> 16;                                                   \
            float4 w0 = wc4[r * 4 + 0], w1 = wc4[r * 4 + 1];                      \
            float4 w2 = wc4[r * 4 + 2], w3 = wc4[r * 4 + 3];                      \
            __half2 h[8];                                                         \
            h[0] = __floats2half2_rn(w0.x * nv, w0.y * nv);                       \
            h[1] = __floats2half2_rn(w0.z * nv, w0.w * nv);                       \
            h[2] = __floats2half2_rn(w1.x * nv, w1.y * nv);                       \
            h[3] = __floats2half2_rn(w1.z * nv, w1.w * nv);                       \
            h[4] = __floats2half2_rn(w2.x * nv, w2.y * nv);                       \
            h[5] = __floats2half2_rn(w2.z * nv, w2.w * nv);                       \
            h[6] = __floats2half2_rn(w3.x * nv, w3.y * nv);                       \
            h[7] = __floats2half2_rn(w3.z * nv, w3.w * nv);                       \
            uint32_t ad = atb[buf] + er * AT_STRIDE;                              \
            *(uint4*)(dynsmem + (ad - smem_u32(dynsmem)))      = *(uint4*)&h[0];  \
            *(uint4*)(dynsmem + (ad - smem_u32(dynsmem)) + 16) = *(uint4*)&h[4];  \
        }                                                                         \
    } while (0)

    for (;;) {
        int nd = 0;
        if (l == 0) nd = atomicAdd(&g_node, 1);
        int d = __shfl_sync(0xFFFFFFFFu, nd, 0);
        if (d >= NNODES) break;

        int k0 = g_off[d], k1 = g_off[d + 1];
        int nch = (k1 - k0 + 15) >> 4;

        float acc[16][4];
#pragma unroll
        for (int j = 0; j < 16; j++)
#pragma unroll
            for (int q = 0; q < 4; q++) acc[j][q] = 0.f;

        if (nch > 0) {
            EDGE_STAGE(0, 0);
            cp_commit();
            if (nch > 1) { EDGE_STAGE(1, 1); }
            cp_commit();

#pragma unroll 1
            for (int c = 0; c < nch; c++) {
                cp_wait<1>();            // chunk c's group arrived
                __syncwarp();
                int buf = c & 1;
                uint32_t af[4];
                ldx4t(af, atb[buf] + a_off);
#pragma unroll
                for (int jj = 0; jj < 8; jj++) {
                    uint32_t bf[4];
                    ldx4t(bf, xsb[buf] + b_off + jj * 32);
                    mma_fp16(acc[2 * jj + 0], af, &bf[0]);
                    mma_fp16(acc[2 * jj + 1], af, &bf[2]);
                }
                __syncwarp();
                if (c + 2 < nch) { EDGE_STAGE(c + 2, buf); }
                cp_commit();             // unconditional: exact group counts
            }
        }

        // epilogue: store G rows (bases) + self-loop x row
        size_t base = (size_t)d * KTOT;
        int row = l >> 2, cc = 2 * (l & 3);
#pragma unroll
        for (int jj = 0; jj < 16; jj++) {
            int col = jj * 8 + cc;
            __half2 h01 = __floats2half2_rn(acc[jj][0], acc[jj][1]);
            __half2 h23 = __floats2half2_rn(acc[jj][2], acc[jj][3]);
            *(__half2*)(g_Ah + base + (size_t)row * 128 + col)       = h01;
            *(__half2*)(g_Ah + base + (size_t)(row + 8) * 128 + col) = h23;
        }
        ((uint2*)(g_Ah + base + KG))[l] = ((const uint2*)(g_xh + (size_t)d * DIN))[l];
    }
#undef EDGE_STAGE
}

// ---------------- fp16 mma GEMM (R8 config): BM=64, BN=128, BK=32, 4-stage ----------------
// 8 warps as 2m x 4n (warp tile 32x32). 3 CTAs/SM. Measured 71us.

__global__ void __launch_bounds__(256, 3) k_gemm_mma(const float* __restrict__ bias,
                                                     float* __restrict__ out)
{
    __shared__ int s_tile;
    int t = threadIdx.x;
    int l = t & 31, wid = t >> 5;

    // re-zero sort counters for next graph replay
    int gid = blockIdx.x * 256 + t;
    if (gid < NNODES) { g_cnt[gid] = 0; g_cur[gid] = 0; }

    uint32_t su = smem_u32(dynsmem);

    int wm = (wid & 1) * 32;
    int wn = (wid >> 1) * 32;

    uint32_t aoff[2], boff[2];
#pragma unroll
    for (int mf = 0; mf < 2; mf++)
        aoff[mf] = (uint32_t)(GSA + (wm + mf * 16 + (l & 15)) * 80 + (l >> 4) * 16);
#pragma unroll
    for (int nb = 0; nb < 2; nb++)
        boff[nb] = (uint32_t)(GSB + (wn + nb * 16 + ((l >> 4) << 3) + (l & 7)) * 80
                              + ((l >> 3) & 1) * 16);

    int arow = t >> 2;                // 0..63
    int aseg = t & 3;                 // 16B segment
    int brow = t >> 1;                // 0..127
    int bseg = (t & 1) * 2;
    uint32_t dA  = (uint32_t)(GSA + arow * 80 + aseg * 16);
    uint32_t dB0 = (uint32_t)(GSB + brow * 80 + bseg * 16);
    uint32_t dB1 = dB0 + 16;
    const __half* pB0 = g_Wh + (size_t)brow * KTOT + bseg * 8;
    const __half* pB1 = pB0 + 8;

    for (;;) {
        __syncthreads();
        if (t == 0) s_tile = atomicAdd(&g_tile, 1);
        __syncthreads();
        int tile = s_tile;
        if (tile >= NTILES) break;
        int tileM = tile * 64;

        const __half* pA = g_Ah + (size_t)(tileM + arow) * KTOT + aseg * 8;

        float acc[2][4][4];
#pragma unroll
        for (int mf = 0; mf < 2; mf++)
#pragma unroll
            for (int nf = 0; nf < 4; nf++)
#pragma unroll
                for (int q = 0; q < 4; q++) acc[mf][nf][q] = 0.f;

#pragma unroll
        for (int p = 0; p < 3; p++) {
            uint32_t sb = su + p * GSTAGE;
            int koff = p * 32;
            cp16(sb + dA,  pA  + koff);
            cp16(sb + dB0, pB0 + koff);
            cp16(sb + dB1, pB1 + koff);
            cp_commit();
        }

        int stg = 0;
#pragma unroll 1
        for (int it = 0; it < KSTAGES; it++) {
            cp_wait<2>();
            __syncthreads();
            if (it + 3 < KSTAGES) {
                int pst = stg + 3; if (pst >= GNSTAGE) pst -= GNSTAGE;
                uint32_t sb = su + pst * GSTAGE;
                int koff = (it + 3) * 32;
                cp16(sb + dA,  pA  + koff);
                cp16(sb + dB0, pB0 + koff);
                cp16(sb + dB1, pB1 + koff);
            }
            cp_commit();

            uint32_t sb = su + stg * GSTAGE;
#pragma unroll
            for (int ks = 0; ks < 2; ks++) {
                uint32_t ah[2][4], bh[4][2];
                ldx4(ah[0], sb + aoff[0] + ks * 32);
                ldx4(ah[1], sb + aoff[1] + ks * 32);
                {
                    uint32_t r[4];
                    ldx4(r, sb + boff[0] + ks * 32);
                    bh[0][0] = r[0]; bh[0][1] = r[1]; bh[1][0] = r[2]; bh[1][1] = r[3];
                    ldx4(r, sb + boff[1] + ks * 32);
                    bh[2][0] = r[0]; bh[2][1] = r[1]; bh[3][0] = r[2]; bh[3][1] = r[3];
                }
#pragma unroll
                for (int mf = 0; mf < 2; mf++)
#pragma unroll
                    for (int nf = 0; nf < 4; nf++)
                        mma_fp16(acc[mf][nf], ah[mf], bh[nf]);
            }
            if (++stg == GNSTAGE) stg = 0;
        }

#pragma unroll
        for (int mf = 0; mf < 2; mf++) {
#pragma unroll
            for (int nf = 0; nf < 4; nf++) {
                int col = wn + nf * 8 + 2 * (l & 3);
                float b0 = bias[col], b1 = bias[col + 1];
                int r0 = tileM + wm + mf * 16 + (l >> 2);
                int r1 = r0 + 8;
                if (r0 < NNODES) {
                    float2 o;
                    o.x = fmaxf(acc[mf][nf][0] + b0, 0.f);
                    o.y = fmaxf(acc[mf][nf][1] + b1, 0.f);
                    *(float2*)(out + (size_t)r0 * DIN + col) = o;
                }
                if (r1 < NNODES) {
                    float2 o;
                    o.x = fmaxf(acc[mf][nf][2] + b0, 0.f);
                    o.y = fmaxf(acc[mf][nf][3] + b1, 0.f);
                    *(float2*)(out + (size_t)r1 * DIN + col) = o;
                }
            }
        }
    }
}

// ---------------- launch ----------------

extern "C" void kernel_launch(void* const* d_in, const int* in_sizes, int n_in,
                              void* d_out, int out_size) {
    const float* x      = (const float*)d_in[0];
    const float* weight = (const float*)d_in[1];
    const float* wcomp  = (const float*)d_in[2];
    const float* bias   = (const float*)d_in[3];
    const float* loopw  = (const float*)d_in[4];
    const float* norm   = (const float*)d_in[5];
    const int*   src    = (const int*)d_in[6];
    const int*   dst    = (const int*)d_in[7];
    const int*   et     = (const int*)d_in[8];
    float* out = (float*)d_out;

    int E = in_sizes[6];

    cudaFuncSetAttribute(k_gemm_mma, cudaFuncAttributeMaxDynamicSharedMemorySize,
                         GEMM_SMEM);
    cudaFuncSetAttribute(k_edge_tc, cudaFuncAttributeMaxDynamicSharedMemorySize,
                         EDGE_SMEM);

    k_histscan<<<(E + 255) / 256, 256>>>(dst, E, weight, loopw, x);
    k_scatter<<<(E + 255) / 256, 256>>>(dst, src, et, norm, E);
    k_edge_tc<<<EDGE_GRID, 256, EDGE_SMEM>>>(wcomp);
    k_gemm_mma<<<GEMM_GRID, 256, GEMM_SMEM>>>(bias, out);
}

// round 14
// speedup vs baseline: 1.0810x; 1.0005x over previous
#include <cuda_runtime.h>
#include <cuda_fp16.h>
#include <cstdint>

#define NNODES 20000
#define NEDGES 640000
#define RREL 64
#define BBASIS 16
#define DIN 128
#define KG 2048
#define KTOT 2176
#define AROWS 20096          /* padded; pad rows stay zero forever */
#define NTILES 313           /* ceil(20000/64) */
#define GEMM_GRID 444
#define EDGE_GRID 296
#define KSTAGES 68           /* 2176 / 32 */

/* GEMM smem stage layout (bytes), 80B row stride keeps ldmatrix conflict-free */
#define GSA 0
#define GSB 5120
#define GSTAGE 15360
#define GNSTAGE 4
#define GEMM_SMEM (GNSTAGE * GSTAGE)   /* 61440 */

/* edge kernel: per-warp double-buffered regions */
#define XS_STRIDE 272        /* 256B row + 16B pad */
#define AT_STRIDE 48         /* 32B row + 16B pad */
#define WXS (16 * XS_STRIDE) /* 4352 */
#define WAT (16 * AT_STRIDE) /* 768  */
#define WBUF (WXS + WAT)     /* 5120 */
#define WREGION (2 * WBUF)   /* 10240 per warp */
#define EDGE_SMEM (8 * WREGION)  /* 81920 */

typedef unsigned long long ull;

// ---------------- helpers ----------------

__device__ __forceinline__ uint32_t smem_u32(const void* p) {
    uint32_t a;
    asm("{ .reg .u64 t; cvta.to.shared.u64 t, %1; cvt.u32.u64 %0, t; }" : "=r"(a) : "l"(p));
    return a;
}

__device__ __forceinline__ void cp16(uint32_t dst, const void* src) {
    asm volatile("cp.async.cg.shared.global [%0], [%1], 16;" :: "r"(dst), "l"(src) : "memory");
}
__device__ __forceinline__ void cp_commit() {
    asm volatile("cp.async.commit_group;" ::: "memory");
}
template <int N>
__device__ __forceinline__ void cp_wait() {
    asm volatile("cp.async.wait_group %0;" :: "n"(N) : "memory");
}

__device__ __forceinline__ void ldx4(uint32_t* r, uint32_t addr) {
    asm volatile("ldmatrix.sync.aligned.m8n8.x4.shared.b16 {%0,%1,%2,%3}, [%4];"
        : "=r"(r[0]), "=r"(r[1]), "=r"(r[2]), "=r"(r[3]) : "r"(addr));
}
__device__ __forceinline__ void ldx4t(uint32_t* r, uint32_t addr) {
    asm volatile("ldmatrix.sync.aligned.m8n8.x4.trans.shared.b16 {%0,%1,%2,%3}, [%4];"
        : "=r"(r[0]), "=r"(r[1]), "=r"(r[2]), "=r"(r[3]) : "r"(addr));
}

__device__ __forceinline__ void mma_fp16(float* d, const uint32_t* a, const uint32_t* b) {
    asm volatile(
        "mma.sync.aligned.m16n8k16.row.col.f32.f16.f16.f32 "
        "{%0,%1,%2,%3}, {%4,%5,%6,%7}, {%8,%9}, {%0,%1,%2,%3};"
        : "+f"(d[0]), "+f"(d[1]), "+f"(d[2]), "+f"(d[3])
        : "r"(a[0]), "r"(a[1]), "r"(a[2]), "r"(a[3]), "r"(b[0]), "r"(b[1]));
}

// ---------------- scratch ----------------
__device__ __half g_Ah[(size_t)AROWS * KTOT];
__device__ __half g_Wh[(size_t)DIN * KTOT];   // [n][k]
__device__ __half g_xh[(size_t)NNODES * DIN]; // x in fp16
__device__ int g_cnt[NNODES];
__device__ int g_cur[NNODES];
__device__ int g_off[NNODES + 1];
__device__ uint2 g_edata[NEDGES];    // sorted packed: {src | et<<16, norm bits}
__device__ int g_tile;
__device__ int g_node;

// ---------------- hist + weight/x conversion ----------------

__global__ void k_histconv(const int* __restrict__ dst, int e,
                           const float* __restrict__ weight,
                           const float* __restrict__ loopw,
                           const float* __restrict__ x) {
    int i = blockIdx.x * blockDim.x + threadIdx.x;
    int nthreads = gridDim.x * blockDim.x;
    if (i < e) atomicAdd(&g_cnt[dst[i]], 1);
    if (i < DIN * KTOT) {
        int n = i & 127;
        int k = i >> 7;
        float w = (k < KG) ? weight[(size_t)k * 128 + n]
                           : loopw[(size_t)(k - KG) * 128 + n];
        g_Wh[(size_t)n * KTOT + k] = __float2half_rn(w);
    }
    for (int j = i; j < NNODES * DIN / 2; j += nthreads) {
        float2 v = ((const float2*)x)[j];
        ((__half2*)g_xh)[j] = __floats2half2_rn(v.x, v.y);
    }
}

// ---------------- exclusive scan (single block) ----------------

__global__ void k_scan() {
    __shared__ int part[256];
    int t = threadIdx.x;
    if (t == 0) { g_tile = 0; g_node = 0; }
    const int chunk = 79;
    int base = t * chunk;
    int s = 0;
    for (int j = 0; j < chunk; j++) {
        int idx = base + j;
        if (idx < NNODES) s += g_cnt[idx];
    }
    part[t] = s;
    __syncthreads();
    for (int d = 1; d < 256; d <<= 1) {
        int v = (t >= d) ? part[t - d] : 0;
        __syncthreads();
        part[t] += v;
        __syncthreads();
    }
    int run = (t == 0) ? 0 : part[t - 1];
    for (int j = 0; j < chunk; j++) {
        int idx = base + j;
        if (idx < NNODES) { g_off[idx] = run; run += g_cnt[idx]; }
    }
    if (t == 255) g_off[NNODES] = run;
}

__global__ void k_scatter(const int* __restrict__ dst, const int* __restrict__ src,
                          const int* __restrict__ et, const float* __restrict__ norm,
                          int e) {
    int i = blockIdx.x * blockDim.x + threadIdx.x;
    if (i < e) {
        int d = dst[i];
        int p = g_off[d] + atomicAdd(&g_cur[d], 1);
        g_edata[p] = make_uint2((uint32_t)src[i] | ((uint32_t)et[i] << 16),
                                __float_as_uint(norm[i]));
    }
}

// ---------------- warp-per-node tensor-core edge accumulation ----------------
// Each WARP owns one dst node: G[16,128] = A[16,deg] @ Xs[deg,128], chunks of
// 16 edges, per-warp double-buffered cp.async, no block barriers in the loop.
// Warps grab nodes in batches of 2 to halve global-atomic round trips.

extern __shared__ char dynsmem[];

__global__ void __launch_bounds__(256, 2) k_edge_tc(const float* __restrict__ wcomp)
{
    __shared__ float wc_s[RREL * BBASIS];

    int t = threadIdx.x;
    int l = t & 31, w = t >> 5;

    for (int i = t; i < RREL * BBASIS; i += 256) wc_s[i] = wcomp[i];
    __syncthreads();
    const float4* wc4 = (const float4*)wc_s;

    uint32_t wbase = smem_u32(dynsmem) + w * WREGION;
    uint32_t xsb[2] = { wbase, wbase + WBUF };
    uint32_t atb[2] = { wbase + WXS, wbase + WBUF + WXS };

    int er = l & 15;          // edge slot this lane stages
    int hh = l >> 4;          // which 128B half of the 256B row
    bool abuild = (l < 16);

    uint32_t a_off = (uint32_t)(((l & 7) + ((l >> 4) & 1) * 8) * AT_STRIDE
                                + ((l >> 3) & 1) * 16);
    uint32_t b_off = (uint32_t)((l & 15) * XS_STRIDE + ((l >> 4) & 1) * 16);

#define EDGE_STAGE(c, buf) do {                                                   \
        int kk = k0 + (c) * 16 + er;                                              \
        uint2 en = __ldg(&g_edata[min(kk, k1 - 1)]);                              \
        bool v = kk < k1;                                                         \
        int s = en.x & 0xFFFF;                                                    \
        uint32_t xdst = xsb[buf] + er * XS_STRIDE + hh * 128;                     \
        const __half* xsrc = g_xh + (size_t)s * DIN + hh * 64;                    \
        _Pragma("unroll")                                                         \
        for (int q = 0; q < 8; q++) cp16(xdst + q * 16, xsrc + q * 8);            \
        if (abuild) {                                                             \
            float nv = v ? __uint_as_float(en.y) : 0.f;                           \
            int r = en.x >> 16;                                                   \
            float4 w0 = wc4[r * 4 + 0], w1 = wc4[r * 4 + 1];                      \
            float4 w2 = wc4[r * 4 + 2], w3 = wc4[r * 4 + 3];                      \
            __half2 h[8];                                                         \
            h[0] = __floats2half2_rn(w0.x * nv, w0.y * nv);                       \
            h[1] = __floats2half2_rn(w0.z * nv, w0.w * nv);                       \
            h[2] = __floats2half2_rn(w1.x * nv, w1.y * nv);                       \
            h[3] = __floats2half2_rn(w1.z * nv, w1.w * nv);                       \
            h[4] = __floats2half2_rn(w2.x * nv, w2.y * nv);                       \
            h[5] = __floats2half2_rn(w2.z * nv, w2.w * nv);                       \
            h[6] = __floats2half2_rn(w3.x * nv, w3.y * nv);                       \
            h[7] = __floats2half2_rn(w3.z * nv, w3.w * nv);                       \
            uint32_t ad = atb[buf] + er * AT_STRIDE;                              \
            *(uint4*)(dynsmem + (ad - smem_u32(dynsmem)))      = *(uint4*)&h[0];  \
            *(uint4*)(dynsmem + (ad - smem_u32(dynsmem)) + 16) = *(uint4*)&h[4];  \
        }                                                                         \
    } while (0)

    for (;;) {
        int nd = 0;
        if (l == 0) nd = atomicAdd(&g_node, 2);
        int d0 = __shfl_sync(0xFFFFFFFFu, nd, 0);
        if (d0 >= NNODES) break;
        int dend = min(d0 + 2, NNODES);

        for (int d = d0; d < dend; d++) {
            int k0 = g_off[d], k1 = g_off[d + 1];
            int nch = (k1 - k0 + 15) >> 4;

            float acc[16][4];
#pragma unroll
            for (int j = 0; j < 16; j++)
#pragma unroll
                for (int q = 0; q < 4; q++) acc[j][q] = 0.f;

            if (nch > 0) {
                EDGE_STAGE(0, 0);
                cp_commit();
                if (nch > 1) { EDGE_STAGE(1, 1); }
                cp_commit();

#pragma unroll 1
                for (int c = 0; c < nch; c++) {
                    cp_wait<1>();            // chunk c's group arrived
                    __syncwarp();
                    int buf = c & 1;
                    uint32_t af[4];
                    ldx4t(af, atb[buf] + a_off);
#pragma unroll
                    for (int jj = 0; jj < 8; jj++) {
                        uint32_t bf[4];
                        ldx4t(bf, xsb[buf] + b_off + jj * 32);
                        mma_fp16(acc[2 * jj + 0], af, &bf[0]);
                        mma_fp16(acc[2 * jj + 1], af, &bf[2]);
                    }
                    __syncwarp();
                    if (c + 2 < nch) { EDGE_STAGE(c + 2, buf); }
                    cp_commit();             // unconditional: exact group counts
                }
            }

            // epilogue: store G rows (bases) + self-loop x row
            size_t base = (size_t)d * KTOT;
            int row = l >> 2, cc = 2 * (l & 3);
#pragma unroll
            for (int jj = 0; jj < 16; jj++) {
                int col = jj * 8 + cc;
                __half2 h01 = __floats2half2_rn(acc[jj][0], acc[jj][1]);
                __half2 h23 = __floats2half2_rn(acc[jj][2], acc[jj][3]);
                *(__half2*)(g_Ah + base + (size_t)row * 128 + col)       = h01;
                *(__half2*)(g_Ah + base + (size_t)(row + 8) * 128 + col) = h23;
            }
            ((uint2*)(g_Ah + base + KG))[l] =
                ((const uint2*)(g_xh + (size_t)d * DIN))[l];
        }
    }
#undef EDGE_STAGE
}

// ---------------- fp16 mma GEMM (R8 config): BM=64, BN=128, BK=32, 4-stage ----------------
// 8 warps as 2m x 4n (warp tile 32x32). 3 CTAs/SM. Measured ~72us.

__global__ void __launch_bounds__(256, 3) k_gemm_mma(const float* __restrict__ bias,
                                                     float* __restrict__ out)
{
    __shared__ int s_tile;
    int t = threadIdx.x;
    int l = t & 31, wid = t >> 5;

    // re-zero sort counters for next graph replay
    int gid = blockIdx.x * 256 + t;
    if (gid < NNODES) { g_cnt[gid] = 0; g_cur[gid] = 0; }

    uint32_t su = smem_u32(dynsmem);

    int wm = (wid & 1) * 32;
    int wn = (wid >> 1) * 32;

    uint32_t aoff[2], boff[2];
#pragma unroll
    for (int mf = 0; mf < 2; mf++)
        aoff[mf] = (uint32_t)(GSA + (wm + mf * 16 + (l & 15)) * 80 + (l >> 4) * 16);
#pragma unroll
    for (int nb = 0; nb < 2; nb++)
        boff[nb] = (uint32_t)(GSB + (wn + nb * 16 + ((l >> 4) << 3) + (l & 7)) * 80
                              + ((l >> 3) & 1) * 16);

    int arow = t >> 2;                // 0..63
    int aseg = t & 3;                 // 16B segment
    int brow = t >> 1;                // 0..127
    int bseg = (t & 1) * 2;
    uint32_t dA  = (uint32_t)(GSA + arow * 80 + aseg * 16);
    uint32_t dB0 = (uint32_t)(GSB + brow * 80 + bseg * 16);
    uint32_t dB1 = dB0 + 16;
    const __half* pB0 = g_Wh + (size_t)brow * KTOT + bseg * 8;
    const __half* pB1 = pB0 + 8;

    for (;;) {
        __syncthreads();
        if (t == 0) s_tile = atomicAdd(&g_tile, 1);
        __syncthreads();
        int tile = s_tile;
        if (tile >= NTILES) break;
        int tileM = tile * 64;

        const __half* pA = g_Ah + (size_t)(tileM + arow) * KTOT + aseg * 8;

        float acc[2][4][4];
#pragma unroll
        for (int mf = 0; mf < 2; mf++)
#pragma unroll
            for (int nf = 0; nf < 4; nf++)
#pragma unroll
                for (int q = 0; q < 4; q++) acc[mf][nf][q] = 0.f;

#pragma unroll
        for (int p = 0; p < 3; p++) {
            uint32_t sb = su + p * GSTAGE;
            int koff = p * 32;
            cp16(sb + dA,  pA  + koff);
            cp16(sb + dB0, pB0 + koff);
            cp16(sb + dB1, pB1 + koff);
            cp_commit();
        }

        int stg = 0;
#pragma unroll 1
        for (int it = 0; it < KSTAGES; it++) {
            cp_wait<2>();
            __syncthreads();
            if (it + 3 < KSTAGES) {
                int pst = stg + 3; if (pst >= GNSTAGE) pst -= GNSTAGE;
                uint32_t sb = su + pst * GSTAGE;
                int koff = (it + 3) * 32;
                cp16(sb + dA,  pA  + koff);
                cp16(sb + dB0, pB0 + koff);
                cp16(sb + dB1, pB1 + koff);
            }
            cp_commit();

            uint32_t sb = su + stg * GSTAGE;
#pragma unroll
            for (int ks = 0; ks < 2; ks++) {
                uint32_t ah[2][4], bh[4][2];
                ldx4(ah[0], sb + aoff[0] + ks * 32);
                ldx4(ah[1], sb + aoff[1] + ks * 32);
                {
                    uint32_t r[4];
                    ldx4(r, sb + boff[0] + ks * 32);
                    bh[0][0] = r[0]; bh[0][1] = r[1]; bh[1][0] = r[2]; bh[1][1] = r[3];
                    ldx4(r, sb + boff[1] + ks * 32);
                    bh[2][0] = r[0]; bh[2][1] = r[1]; bh[3][0] = r[2]; bh[3][1] = r[3];
                }
#pragma unroll
                for (int mf = 0; mf < 2; mf++)
#pragma unroll
                    for (int nf = 0; nf < 4; nf++)
                        mma_fp16(acc[mf][nf], ah[mf], bh[nf]);
            }
            if (++stg == GNSTAGE) stg = 0;
        }

#pragma unroll
        for (int mf = 0; mf < 2; mf++) {
#pragma unroll
            for (int nf = 0; nf < 4; nf++) {
                int col = wn + nf * 8 + 2 * (l & 3);
                float b0 = bias[col], b1 = bias[col + 1];
                int r0 = tileM + wm + mf * 16 + (l >> 2);
                int r1 = r0 + 8;
                if (r0 < NNODES) {
                    float2 o;
                    o.x = fmaxf(acc[mf][nf][0] + b0, 0.f);
                    o.y = fmaxf(acc[mf][nf][1] + b1, 0.f);
                    *(float2*)(out + (size_t)r0 * DIN + col) = o;
                }
                if (r1 < NNODES) {
                    float2 o;
                    o.x = fmaxf(acc[mf][nf][2] + b0, 0.f);
                    o.y = fmaxf(acc[mf][nf][3] + b1, 0.f);
                    *(float2*)(out + (size_t)r1 * DIN + col) = o;
                }
            }
        }
    }
}

// ---------------- launch ----------------

extern "C" void kernel_launch(void* const* d_in, const int* in_sizes, int n_in,
                              void* d_out, int out_size) {
    const float* x      = (const float*)d_in[0];
    const float* weight = (const float*)d_in[1];
    const float* wcomp  = (const float*)d_in[2];
    const float* bias   = (const float*)d_in[3];
    const float* loopw  = (const float*)d_in[4];
    const float* norm   = (const float*)d_in[5];
    const int*   src    = (const int*)d_in[6];
    const int*   dst    = (const int*)d_in[7];
    const int*   et     = (const int*)d_in[8];
    float* out = (float*)d_out;

    int E = in_sizes[6];

    cudaFuncSetAttribute(k_gemm_mma, cudaFuncAttributeMaxDynamicSharedMemorySize,
                         GEMM_SMEM);
    cudaFuncSetAttribute(k_edge_tc, cudaFuncAttributeMaxDynamicSharedMemorySize,
                         EDGE_SMEM);

    k_histconv<<<(E + 255) / 256, 256>>>(dst, E, weight, loopw, x);
    k_scan<<<1, 256>>>();
    k_scatter<<<(E + 255) / 256, 256>>>(dst, src, et, norm, E);
    k_edge_tc<<<EDGE_GRID, 256, EDGE_SMEM>>>(wcomp);
    k_gemm_mma<<<GEMM_GRID, 256, GEMM_SMEM>>>(bias, out);
}

// round 15
// speedup vs baseline: 1.2585x; 1.1643x over previous
#include <cuda_runtime.h>
#include <cuda_fp16.h>
#include <cstdint>

#define NNODES 20000
#define NEDGES 640000
#define RREL 64
#define BBASIS 16
#define DIN 128
#define KG 2048
#define KTOT 2176
#define AROWS 20096          /* padded; pad rows stay zero forever */
#define NTILES 313           /* ceil(20000/64) */
#define GEMM_GRID 444
#define EDGE_GRID 296
#define KSTAGES 68           /* 2176 / 32 */

/* GEMM smem stage layout (bytes), 80B row stride keeps ldmatrix conflict-free */
#define GSA 0
#define GSB 5120
#define GSTAGE 15360
#define GNSTAGE 4
#define GEMM_SMEM (GNSTAGE * GSTAGE)   /* 61440 */

/* edge kernel: per-warp double-buffered regions */
#define XS_STRIDE 272        /* 256B row + 16B pad */
#define AT_STRIDE 48         /* 32B row + 16B pad */
#define WXS (16 * XS_STRIDE) /* 4352 */
#define WAT (16 * AT_STRIDE) /* 768  */
#define WBUF (WXS + WAT)     /* 5120 */
#define WREGION (2 * WBUF)   /* 10240 per warp */
#define EDGE_SMEM (8 * WREGION)  /* 81920 */

typedef unsigned long long ull;

// ---------------- helpers ----------------

__device__ __forceinline__ uint32_t smem_u32(const void* p) {
    uint32_t a;
    asm("{ .reg .u64 t; cvta.to.shared.u64 t, %1; cvt.u32.u64 %0, t; }" : "=r"(a) : "l"(p));
    return a;
}

__device__ __forceinline__ void cp16(uint32_t dst, const void* src) {
    asm volatile("cp.async.cg.shared.global [%0], [%1], 16;" :: "r"(dst), "l"(src) : "memory");
}
__device__ __forceinline__ void cp_commit() {
    asm volatile("cp.async.commit_group;" ::: "memory");
}
template <int N>
__device__ __forceinline__ void cp_wait() {
    asm volatile("cp.async.wait_group %0;" :: "n"(N) : "memory");
}

__device__ __forceinline__ void ldx4(uint32_t* r, uint32_t addr) {
    asm volatile("ldmatrix.sync.aligned.m8n8.x4.shared.b16 {%0,%1,%2,%3}, [%4];"
        : "=r"(r[0]), "=r"(r[1]), "=r"(r[2]), "=r"(r[3]) : "r"(addr));
}
__device__ __forceinline__ void ldx4t(uint32_t* r, uint32_t addr) {
    asm volatile("ldmatrix.sync.aligned.m8n8.x4.trans.shared.b16 {%0,%1,%2,%3}, [%4];"
        : "=r"(r[0]), "=r"(r[1]), "=r"(r[2]), "=r"(r[3]) : "r"(addr));
}

__device__ __forceinline__ void mma_fp16(float* d, const uint32_t* a, const uint32_t* b) {
    asm volatile(
        "mma.sync.aligned.m16n8k16.row.col.f32.f16.f16.f32 "
        "{%0,%1,%2,%3}, {%4,%5,%6,%7}, {%8,%9}, {%0,%1,%2,%3};"
        : "+f"(d[0]), "+f"(d[1]), "+f"(d[2]), "+f"(d[3])
        : "r"(a[0]), "r"(a[1]), "r"(a[2]), "r"(a[3]), "r"(b[0]), "r"(b[1]));
}

// ---------------- scratch ----------------
__device__ __half g_Ah[(size_t)AROWS * KTOT];
__device__ __half g_Wh[(size_t)DIN * KTOT];   // [n][k]
__device__ __half g_xh[(size_t)NNODES * DIN]; // x in fp16
__device__ int g_cnt[NNODES];
__device__ int g_cur[NNODES];
__device__ int g_off[NNODES + 1];
__device__ uint2 g_edata[NEDGES];    // sorted packed: {src | et<<16, norm bits}
__device__ int g_tile;
__device__ int g_node;

// ---------------- hist + weight/x conversion ----------------

__global__ void k_histconv(const int* __restrict__ dst, int e,
                           const float* __restrict__ weight,
                           const float* __restrict__ loopw,
                           const float* __restrict__ x) {
    int i = blockIdx.x * blockDim.x + threadIdx.x;
    int nthreads = gridDim.x * blockDim.x;
    if (i < e) atomicAdd(&g_cnt[dst[i]], 1);
    if (i < DIN * KTOT) {
        int n = i & 127;
        int k = i >> 7;
        float w = (k < KG) ? weight[(size_t)k * 128 + n]
                           : loopw[(size_t)(k - KG) * 128 + n];
        g_Wh[(size_t)n * KTOT + k] = __float2half_rn(w);
    }
    for (int j = i; j < NNODES * DIN / 2; j += nthreads) {
        float2 v = ((const float2*)x)[j];
        ((__half2*)g_xh)[j] = __floats2half2_rn(v.x, v.y);
    }
}

// ---------------- exclusive scan (single block) ----------------

__global__ void k_scan() {
    __shared__ int part[256];
    int t = threadIdx.x;
    if (t == 0) { g_tile = 0; g_node = 0; }
    const int chunk = 79;
    int base = t * chunk;
    int s = 0;
    for (int j = 0; j < chunk; j++) {
        int idx = base + j;
        if (idx < NNODES) s += g_cnt[idx];
    }
    part[t] = s;
    __syncthreads();
    for (int d = 1; d < 256; d <<= 1) {
        int v = (t >= d) ? part[t - d] : 0;
        __syncthreads();
        part[t] += v;
        __syncthreads();
    }
    int run = (t == 0) ? 0 : part[t - 1];
    for (int j = 0; j < chunk; j++) {
        int idx = base + j;
        if (idx < NNODES) { g_off[idx] = run; run += g_cnt[idx]; }
    }
    if (t == 255) g_off[NNODES] = run;
}

__global__ void k_scatter(const int* __restrict__ dst, const int* __restrict__ src,
                          const int* __restrict__ et, const float* __restrict__ norm,
                          int e) {
    int i = blockIdx.x * blockDim.x + threadIdx.x;
    if (i < e) {
        int d = dst[i];
        int p = g_off[d] + atomicAdd(&g_cur[d], 1);
        g_edata[p] = make_uint2((uint32_t)src[i] | ((uint32_t)et[i] << 16),
                                __float_as_uint(norm[i]));
    }
}

// ---------------- warp-per-node tensor-core edge accumulation ----------------
// Each WARP owns one dst node: G[16,128] = A[16,deg] @ Xs[deg,128], 16-edge
// chunks, per-warp double-buffered cp.async, no block barriers in the loop.
// Gather is LINE-COALESCED: cp16 instr i covers 2 complete 256B rows (lanes
// 0-15 = row 2i's 16 segments, lanes 16-31 = row 2i+1) -> 4 L1 wavefronts per
// instr (was 32). Src node ids routed to lanes by shuffle.

extern __shared__ char dynsmem[];

__global__ void __launch_bounds__(256, 2) k_edge_tc(const float* __restrict__ wcomp)
{
    __shared__ float wc_s[RREL * BBASIS];

    int t = threadIdx.x;
    int l = t & 31, w = t >> 5;

    for (int i = t; i < RREL * BBASIS; i += 256) wc_s[i] = wcomp[i];
    __syncthreads();
    const float4* wc4 = (const float4*)wc_s;

    char* wptr = dynsmem + w * WREGION;
    uint32_t wbase = smem_u32(wptr);
    uint32_t xsb[2] = { wbase, wbase + WBUF };
    uint32_t atb[2] = { wbase + WXS, wbase + WBUF + WXS };
    char* atp[2] = { wptr + WXS, wptr + WBUF + WXS };

    int er = l & 15;          // slot owned for record + segment index
    int hh = l >> 4;          // 0/1: A-half built + row parity gathered

    uint32_t a_off = (uint32_t)(((l & 7) + ((l >> 4) & 1) * 8) * AT_STRIDE
                                + ((l >> 3) & 1) * 16);
    uint32_t b_off = (uint32_t)((l & 15) * XS_STRIDE + ((l >> 4) & 1) * 16);

#define EDGE_STAGE(c, buf) do {                                                   \
        int kk = k0 + (c) * 16 + er;                                              \
        uint2 en = __ldg(&g_edata[min(kk, k1 - 1)]);                              \
        bool v = kk < k1;                                                         \
        int s_own = en.x & 0xFFFF;                                                \
        /* A build: lane (er,hh) builds half hh of slot er's column */            \
        {                                                                         \
            float nv = v ? __uint_as_float(en.y) : 0.f;                           \
            int r = en.x >> 16;                                                   \
            float4 wA = wc4[r * 4 + 2 * hh];                                      \
            float4 wB = wc4[r * 4 + 2 * hh + 1];                                  \
            __half2 h[4];                                                         \
            h[0] = __floats2half2_rn(wA.x * nv, wA.y * nv);                       \
            h[1] = __floats2half2_rn(wA.z * nv, wA.w * nv);                       \
            h[2] = __floats2half2_rn(wB.x * nv, wB.y * nv);                       \
            h[3] = __floats2half2_rn(wB.z * nv, wB.w * nv);                       \
            *(uint4*)(atp[buf] + er * AT_STRIDE + hh * 16) = *(uint4*)h;          \
        }                                                                         \
        /* coalesced gather: instr i covers rows 2i (lanes 0-15) and 2i+1 */      \
        _Pragma("unroll")                                                         \
        for (int i = 0; i < 8; i++) {                                             \
            int slot = 2 * i + hh;                                                \
            int ss = __shfl_sync(0xFFFFFFFFu, s_own, slot);                       \
            cp16(xsb[buf] + slot * XS_STRIDE + er * 16,                           \
                 g_xh + (size_t)ss * DIN + er * 8);                               \
        }                                                                         \
    } while (0)

    for (;;) {
        int nd = 0;
        if (l == 0) nd = atomicAdd(&g_node, 2);
        int d0 = __shfl_sync(0xFFFFFFFFu, nd, 0);
        if (d0 >= NNODES) break;
        int dend = min(d0 + 2, NNODES);

        for (int d = d0; d < dend; d++) {
            int k0 = g_off[d], k1 = g_off[d + 1];
            int nch = (k1 - k0 + 15) >> 4;

            float acc[16][4];
#pragma unroll
            for (int j = 0; j < 16; j++)
#pragma unroll
                for (int q = 0; q < 4; q++) acc[j][q] = 0.f;

            if (nch > 0) {
                EDGE_STAGE(0, 0);
                cp_commit();
                if (nch > 1) { EDGE_STAGE(1, 1); }
                cp_commit();

#pragma unroll 1
                for (int c = 0; c < nch; c++) {
                    cp_wait<1>();            // chunk c's group arrived
                    __syncwarp();
                    int buf = c & 1;
                    uint32_t af[4];
                    ldx4t(af, atb[buf] + a_off);
#pragma unroll
                    for (int jj = 0; jj < 8; jj++) {
                        uint32_t bf[4];
                        ldx4t(bf, xsb[buf] + b_off + jj * 32);
                        mma_fp16(acc[2 * jj + 0], af, &bf[0]);
                        mma_fp16(acc[2 * jj + 1], af, &bf[2]);
                    }
                    __syncwarp();
                    if (c + 2 < nch) { EDGE_STAGE(c + 2, buf); }
                    cp_commit();             // unconditional: exact group counts
                }
            }

            // epilogue: store G rows (bases) + self-loop x row
            size_t base = (size_t)d * KTOT;
            int row = l >> 2, cc = 2 * (l & 3);
#pragma unroll
            for (int jj = 0; jj < 16; jj++) {
                int col = jj * 8 + cc;
                __half2 h01 = __floats2half2_rn(acc[jj][0], acc[jj][1]);
                __half2 h23 = __floats2half2_rn(acc[jj][2], acc[jj][3]);
                *(__half2*)(g_Ah + base + (size_t)row * 128 + col)       = h01;
                *(__half2*)(g_Ah + base + (size_t)(row + 8) * 128 + col) = h23;
            }
            ((uint2*)(g_Ah + base + KG))[l] =
                ((const uint2*)(g_xh + (size_t)d * DIN))[l];
        }
    }
#undef EDGE_STAGE
}

// ---------------- fp16 mma GEMM (R8 config): BM=64, BN=128, BK=32, 4-stage ----------------
// 8 warps as 2m x 4n (warp tile 32x32). 3 CTAs/SM. Measured ~72us.

__global__ void __launch_bounds__(256, 3) k_gemm_mma(const float* __restrict__ bias,
                                                     float* __restrict__ out)
{
    __shared__ int s_tile;
    int t = threadIdx.x;
    int l = t & 31, wid = t >> 5;

    // re-zero sort counters for next graph replay
    int gid = blockIdx.x * 256 + t;
    if (gid < NNODES) { g_cnt[gid] = 0; g_cur[gid] = 0; }

    uint32_t su = smem_u32(dynsmem);

    int wm = (wid & 1) * 32;
    int wn = (wid >> 1) * 32;

    uint32_t aoff[2], boff[2];
#pragma unroll
    for (int mf = 0; mf < 2; mf++)
        aoff[mf] = (uint32_t)(GSA + (wm + mf * 16 + (l & 15)) * 80 + (l >> 4) * 16);
#pragma unroll
    for (int nb = 0; nb < 2; nb++)
        boff[nb] = (uint32_t)(GSB + (wn + nb * 16 + ((l >> 4) << 3) + (l & 7)) * 80
                              + ((l >> 3) & 1) * 16);

    int arow = t >> 2;                // 0..63
    int aseg = t & 3;                 // 16B segment
    int brow = t >> 1;                // 0..127
    int bseg = (t & 1) * 2;
    uint32_t dA  = (uint32_t)(GSA + arow * 80 + aseg * 16);
    uint32_t dB0 = (uint32_t)(GSB + brow * 80 + bseg * 16);
    uint32_t dB1 = dB0 + 16;
    const __half* pB0 = g_Wh + (size_t)brow * KTOT + bseg * 8;
    const __half* pB1 = pB0 + 8;

    for (;;) {
        __syncthreads();
        if (t == 0) s_tile = atomicAdd(&g_tile, 1);
        __syncthreads();
        int tile = s_tile;
        if (tile >= NTILES) break;
        int tileM = tile * 64;

        const __half* pA = g_Ah + (size_t)(tileM + arow) * KTOT + aseg * 8;

        float acc[2][4][4];
#pragma unroll
        for (int mf = 0; mf < 2; mf++)
#pragma unroll
            for (int nf = 0; nf < 4; nf++)
#pragma unroll
                for (int q = 0; q < 4; q++) acc[mf][nf][q] = 0.f;

#pragma unroll
        for (int p = 0; p < 3; p++) {
            uint32_t sb = su + p * GSTAGE;
            int koff = p * 32;
            cp16(sb + dA,  pA  + koff);
            cp16(sb + dB0, pB0 + koff);
            cp16(sb + dB1, pB1 + koff);
            cp_commit();
        }

        int stg = 0;
#pragma unroll 1
        for (int it = 0; it < KSTAGES; it++) {
            cp_wait<2>();
            __syncthreads();
            if (it + 3 < KSTAGES) {
                int pst = stg + 3; if (pst >= GNSTAGE) pst -= GNSTAGE;
                uint32_t sb = su + pst * GSTAGE;
                int koff = (it + 3) * 32;
                cp16(sb + dA,  pA  + koff);
                cp16(sb + dB0, pB0 + koff);
                cp16(sb + dB1, pB1 + koff);
            }
            cp_commit();

            uint32_t sb = su + stg * GSTAGE;
#pragma unroll
            for (int ks = 0; ks < 2; ks++) {
                uint32_t ah[2][4], bh[4][2];
                ldx4(ah[0], sb + aoff[0] + ks * 32);
                ldx4(ah[1], sb + aoff[1] + ks * 32);
                {
                    uint32_t r[4];
                    ldx4(r, sb + boff[0] + ks * 32);
                    bh[0][0] = r[0]; bh[0][1] = r[1]; bh[1][0] = r[2]; bh[1][1] = r[3];
                    ldx4(r, sb + boff[1] + ks * 32);
                    bh[2][0] = r[0]; bh[2][1] = r[1]; bh[3][0] = r[2]; bh[3][1] = r[3];
                }
#pragma unroll
                for (int mf = 0; mf < 2; mf++)
#pragma unroll
                    for (int nf = 0; nf < 4; nf++)
                        mma_fp16(acc[mf][nf], ah[mf], bh[nf]);
            }
            if (++stg == GNSTAGE) stg = 0;
        }

#pragma unroll
        for (int mf = 0; mf < 2; mf++) {
#pragma unroll
            for (int nf = 0; nf < 4; nf++) {
                int col = wn + nf * 8 + 2 * (l & 3);
                float b0 = bias[col], b1 = bias[col + 1];
                int r0 = tileM + wm + mf * 16 + (l >> 2);
                int r1 = r0 + 8;
                if (r0 < NNODES) {
                    float2 o;
                    o.x = fmaxf(acc[mf][nf][0] + b0, 0.f);
                    o.y = fmaxf(acc[mf][nf][1] + b1, 0.f);
                    *(float2*)(out + (size_t)r0 * DIN + col) = o;
                }
                if (r1 < NNODES) {
                    float2 o;
                    o.x = fmaxf(acc[mf][nf][2] + b0, 0.f);
                    o.y = fmaxf(acc[mf][nf][3] + b1, 0.f);
                    *(float2*)(out + (size_t)r1 * DIN + col) = o;
                }
            }
        }
    }
}

// ---------------- launch ----------------

extern "C" void kernel_launch(void* const* d_in, const int* in_sizes, int n_in,
                              void* d_out, int out_size) {
    const float* x      = (const float*)d_in[0];
    const float* weight = (const float*)d_in[1];
    const float* wcomp  = (const float*)d_in[2];
    const float* bias   = (const float*)d_in[3];
    const float* loopw  = (const float*)d_in[4];
    const float* norm   = (const float*)d_in[5];
    const int*   src    = (const int*)d_in[6];
    const int*   dst    = (const int*)d_in[7];
    const int*   et     = (const int*)d_in[8];
    float* out = (float*)d_out;

    int E = in_sizes[6];

    cudaFuncSetAttribute(k_gemm_mma, cudaFuncAttributeMaxDynamicSharedMemorySize,
                         GEMM_SMEM);
    cudaFuncSetAttribute(k_edge_tc, cudaFuncAttributeMaxDynamicSharedMemorySize,
                         EDGE_SMEM);

    k_histconv<<<(E + 255) / 256, 256>>>(dst, E, weight, loopw, x);
    k_scan<<<1, 256>>>();
    k_scatter<<<(E + 255) / 256, 256>>>(dst, src, et, norm, E);
    k_edge_tc<<<EDGE_GRID, 256, EDGE_SMEM>>>(wcomp);
    k_gemm_mma<<<GEMM_GRID, 256, GEMM_SMEM>>>(bias, out);
}